// round 7
// baseline (speedup 1.0000x reference)
#include <cuda_runtime.h>
#include <math.h>

#define B_ 8
#define T_ 2048
#define C_ 1024
#define H_ 64
#define NROWS (B_ * T_)   // 16384

__device__ float g_q[NROWS * H_];
__device__ float g_k[NROWS * H_];
__device__ float g_v[NROWS * H_];
__device__ float g_res[NROWS * H_];
__device__ float g_rowsum[NROWS];
__device__ float g_attn_scratch[(size_t)B_ * T_ * T_];

// ---- tf32 helpers -----------------------------------------------------------
__device__ __forceinline__ unsigned tf32(float f) {
    unsigned r;
    asm("cvt.rna.tf32.f32 %0, %1;" : "=r"(r) : "f"(f));
    return r;
}
__device__ __forceinline__ uint4 tf32x4(float4 f) {
    uint4 u;
    u.x = tf32(f.x); u.y = tf32(f.y); u.z = tf32(f.z); u.w = tf32(f.w);
    return u;
}
// D += A(16x8,row) * B(8x8,col); tf32 in, fp32 accum
__device__ __forceinline__ void mma8(float* c, const unsigned* a, const unsigned* b) {
    asm("mma.sync.aligned.m16n8k8.row.col.f32.tf32.tf32.f32 "
        "{%0,%1,%2,%3},{%4,%5,%6,%7},{%8,%9},{%0,%1,%2,%3};"
        : "+f"(c[0]), "+f"(c[1]), "+f"(c[2]), "+f"(c[3])
        : "r"(a[0]), "r"(a[1]), "r"(a[2]), "r"(a[3]), "r"(b[0]), "r"(b[1]));
}

// ---------------------------------------------------------------------------
// Kernel 1: QKV projection. grid=(128, 3), block=128 (4 warps: 2m x 2n).
// Block tile 128m x 64h, K-chunk 64. Warp tile 64m x 32h (mi=4, nj=4).
// LDS/MMA = 1.5 (was 2.0). smem 53KB -> 4 CTAs/SM.
// ---------------------------------------------------------------------------
#define PROJ_SMEM (128 * 68 * 4 + 64 * 72 * 4)   // 53248 B
__global__ __launch_bounds__(128) void proj_kernel(const float* __restrict__ x,
                                                   const float* __restrict__ Wq,
                                                   const float* __restrict__ Wk,
                                                   const float* __restrict__ Wv) {
    extern __shared__ unsigned smu[];
    unsigned* Xs = smu;             // [128][68]
    unsigned* Ws = smu + 128 * 68;  // [64][72]

    const float* W; float* out;
    if (blockIdx.y == 0)      { W = Wq; out = g_q; }
    else if (blockIdx.y == 1) { W = Wk; out = g_k; }
    else                      { W = Wv; out = g_v; }

    const int row0 = blockIdx.x * 128;
    const int tid  = threadIdx.x;
    const int warp = tid >> 5;
    const int lane = tid & 31;
    const int g    = lane >> 2;    // 0..7
    const int tig  = lane & 3;     // 0..3
    const int wm   = warp >> 1;    // 0..1 (m)
    const int wn   = warp & 1;     // 0..1 (n)

    float acc[4][4][4] = {};

    for (int k0 = 0; k0 < C_; k0 += 64) {
        #pragma unroll
        for (int it = 0; it < 16; it++) {
            int idx = tid + it * 128;         // 2048 float4 = 128 x 16
            int r = idx >> 4, c4 = idx & 15;
            *(uint4*)&Xs[r * 68 + c4 * 4] =
                tf32x4(*(const float4*)&x[(size_t)(row0 + r) * C_ + k0 + c4 * 4]);
        }
        #pragma unroll
        for (int it = 0; it < 8; it++) {
            int idx = tid + it * 128;         // 1024 float4 = 64 x 16
            int r = idx >> 4, c4 = idx & 15;
            *(uint4*)&Ws[r * 72 + c4 * 4] =
                tf32x4(*(const float4*)&W[(size_t)(k0 + r) * H_ + c4 * 4]);
        }
        __syncthreads();

        #pragma unroll
        for (int k8 = 0; k8 < 8; k8++) {
            const int kb = k8 * 8;
            unsigned a[4][4];
            #pragma unroll
            for (int mi = 0; mi < 4; mi++) {
                int m0 = wm * 64 + mi * 16;
                a[mi][0] = Xs[(m0 + g) * 68 + kb + tig];
                a[mi][1] = Xs[(m0 + g + 8) * 68 + kb + tig];
                a[mi][2] = Xs[(m0 + g) * 68 + kb + tig + 4];
                a[mi][3] = Xs[(m0 + g + 8) * 68 + kb + tig + 4];
            }
            #pragma unroll
            for (int nj = 0; nj < 4; nj++) {
                int n0 = wn * 32 + nj * 8;
                unsigned b[2];
                b[0] = Ws[(kb + tig) * 72 + n0 + g];
                b[1] = Ws[(kb + tig + 4) * 72 + n0 + g];
                #pragma unroll
                for (int mi = 0; mi < 4; mi++) mma8(acc[mi][nj], a[mi], b);
            }
        }
        __syncthreads();
    }

    #pragma unroll
    for (int mi = 0; mi < 4; mi++) {
        #pragma unroll
        for (int nj = 0; nj < 4; nj++) {
            int m0 = row0 + wm * 64 + mi * 16;
            int n0 = wn * 32 + nj * 8 + tig * 2;
            float* c = acc[mi][nj];
            *(float2*)&out[(size_t)(m0 + g) * H_ + n0]     = make_float2(c[0], c[1]);
            *(float2*)&out[(size_t)(m0 + g + 8) * H_ + n0] = make_float2(c[2], c[3]);
        }
    }
}

// ---------------------------------------------------------------------------
// Kernel 2: E = exp(Q@K^T / 32) lower tiles (zeros upper), rowsum atomics.
// grid=(16 s,32 t,8 b), block=128 (4 warps along s). Tile 64t x 128s.
// (unchanged from round 6)
// ---------------------------------------------------------------------------
#define SCORES_SMEM (64 * 68 * 4 + 128 * 68 * 4)   // 52224 B
__global__ __launch_bounds__(128, 4) void scores_kernel(float* __restrict__ attn) {
    const int s_t = blockIdx.x, t_t = blockIdx.y;
    const int b = blockIdx.z;
    const int t0 = t_t * 64, s0 = s_t * 128;
    const int tid = threadIdx.x;

    if (s0 > t0 + 63) {  // strictly-upper tile: zero fill
        #pragma unroll
        for (int it = 0; it < 16; it++) {
            int idx = tid + it * 128;       // 2048 quads = 64 x 32
            int r = idx >> 5, c4 = idx & 31;
            *(float4*)&attn[((size_t)b * T_ + t0 + r) * T_ + s0 + c4 * 4] =
                make_float4(0.f, 0.f, 0.f, 0.f);
        }
        return;
    }

    extern __shared__ unsigned smu[];
    unsigned* Qs = smu;            // [64][68]
    unsigned* Ks = smu + 64 * 68;  // [128][68]

    const float* q = g_q + (size_t)b * T_ * H_;
    const float* k = g_k + (size_t)b * T_ * H_;

    #pragma unroll
    for (int it = 0; it < 8; it++) {
        int idx = tid + it * 128;          // 1024 float4 = 64 x 16
        int r = idx >> 4, c4 = idx & 15;
        *(uint4*)&Qs[r * 68 + c4 * 4] =
            tf32x4(*(const float4*)&q[(size_t)(t0 + r) * H_ + c4 * 4]);
    }
    #pragma unroll
    for (int it = 0; it < 16; it++) {
        int idx = tid + it * 128;          // 2048 float4 = 128 x 16
        int r = idx >> 4, c4 = idx & 15;
        *(uint4*)&Ks[r * 68 + c4 * 4] =
            tf32x4(*(const float4*)&k[(size_t)(s0 + r) * H_ + c4 * 4]);
    }
    __syncthreads();

    const int warp = tid >> 5;
    const int lane = tid & 31;
    const int g    = lane >> 2;
    const int tig  = lane & 3;

    float acc[4][4][4] = {};
    #pragma unroll
    for (int k8 = 0; k8 < 8; k8++) {
        const int kb = k8 * 8;
        unsigned a[4][4];
        #pragma unroll
        for (int mi = 0; mi < 4; mi++) {
            int m0 = mi * 16;
            a[mi][0] = Qs[(m0 + g) * 68 + kb + tig];
            a[mi][1] = Qs[(m0 + g + 8) * 68 + kb + tig];
            a[mi][2] = Qs[(m0 + g) * 68 + kb + tig + 4];
            a[mi][3] = Qs[(m0 + g + 8) * 68 + kb + tig + 4];
        }
        #pragma unroll
        for (int nj = 0; nj < 4; nj++) {
            int n0 = warp * 32 + nj * 8;
            unsigned bb[2];
            bb[0] = Ks[(n0 + g) * 68 + kb + tig];
            bb[1] = Ks[(n0 + g) * 68 + kb + tig + 4];
            #pragma unroll
            for (int mi = 0; mi < 4; mi++) mma8(acc[mi][nj], a[mi], bb);
        }
    }

    const float sc = 0.03125f;  // 1/sqrt(1024)
    const bool need_mask = (s0 + 127 > t0);
    #pragma unroll
    for (int mi = 0; mi < 4; mi++) {
        const int trow0 = t0 + mi * 16 + g;
        const int trow1 = trow0 + 8;
        float rs0 = 0.f, rs1 = 0.f;
        #pragma unroll
        for (int nj = 0; nj < 4; nj++) {
            int col = s0 + warp * 32 + nj * 8 + tig * 2;
            float* c = acc[mi][nj];
            float e0 = (!need_mask || col     <= trow0) ? __expf(c[0] * sc) : 0.f;
            float e1 = (!need_mask || col + 1 <= trow0) ? __expf(c[1] * sc) : 0.f;
            float e2 = (!need_mask || col     <= trow1) ? __expf(c[2] * sc) : 0.f;
            float e3 = (!need_mask || col + 1 <= trow1) ? __expf(c[3] * sc) : 0.f;
            rs0 += e0 + e1; rs1 += e2 + e3;
            *(float2*)&attn[((size_t)b * T_ + trow0) * T_ + col] = make_float2(e0, e1);
            *(float2*)&attn[((size_t)b * T_ + trow1) * T_ + col] = make_float2(e2, e3);
        }
        rs0 += __shfl_xor_sync(0xffffffffu, rs0, 1);
        rs0 += __shfl_xor_sync(0xffffffffu, rs0, 2);
        rs1 += __shfl_xor_sync(0xffffffffu, rs1, 1);
        rs1 += __shfl_xor_sync(0xffffffffu, rs1, 2);
        if (tig == 0) {
            atomicAdd(&g_rowsum[(size_t)b * T_ + trow0], rs0);
            atomicAdd(&g_rowsum[(size_t)b * T_ + trow1], rs1);
        }
    }
}

// ---------------------------------------------------------------------------
// Kernel 3: res += (attn/rowsum) @ V, split-K over 512-wide s-spans.
// Fused normalization (each attn element owned by exactly one span CTA).
// grid=(4 spans, 16 t-tiles desc, 8 b), block=128 (4 warps m-split).
// Block tile 128t x 64h; warp tile 32t x 64h (mi=2, nj=8). LDS/MMA = 1.5.
// ---------------------------------------------------------------------------
#define AV_SMEM (128 * 68 * 4 + 64 * 72 * 4 + 128 * 4)   // 53760 B
__global__ __launch_bounds__(128) void av_kernel(float* __restrict__ attn,
                                                 float* __restrict__ res) {
    const int sc   = blockIdx.x;
    const int t_t  = 15 - blockIdx.y;   // big tiles first
    const int b    = blockIdx.z;
    const int t0   = t_t * 128;
    if (sc * 512 > t0 + 127) return;

    extern __shared__ unsigned smu[];
    unsigned* As = smu;             // [128 t][68 s] tf32
    unsigned* Vs = smu + 128 * 68;  // [64 s][72 h] tf32
    float* sinv  = (float*)(smu + 128 * 68 + 64 * 72);

    const int tid = threadIdx.x;
    sinv[tid] = 1.f / g_rowsum[(size_t)b * T_ + t0 + tid];
    __syncthreads();

    const float* v = g_v + (size_t)b * T_ * H_;
    const int warp = tid >> 5;
    const int lane = tid & 31;
    const int g    = lane >> 2;
    const int tig  = lane & 3;

    float acc[2][8][4] = {};

    #pragma unroll
    for (int c2 = 0; c2 < 8; c2++) {
        const int s0 = sc * 512 + c2 * 64;
        if (s0 > t0 + 127) break;

        #pragma unroll
        for (int it = 0; it < 16; it++) {
            int idx = tid + it * 128;          // 2048 float4 = 128 x 16
            int r = idx >> 4, c4 = idx & 15;
            float* ap = &attn[((size_t)b * T_ + t0 + r) * T_ + s0 + c4 * 4];
            float4 f = *(const float4*)ap;
            float iv = sinv[r];
            f = make_float4(f.x * iv, f.y * iv, f.z * iv, f.w * iv);
            *(float4*)ap = f;                  // normalized fp32 back to gmem
            *(uint4*)&As[r * 68 + c4 * 4] = tf32x4(f);
        }
        #pragma unroll
        for (int it = 0; it < 8; it++) {
            int idx = tid + it * 128;          // 1024 float4 = 64 x 16
            int r = idx >> 4, c4 = idx & 15;
            *(uint4*)&Vs[r * 72 + c4 * 4] =
                tf32x4(*(const float4*)&v[(size_t)(s0 + r) * H_ + c4 * 4]);
        }
        __syncthreads();

        #pragma unroll
        for (int k8 = 0; k8 < 8; k8++) {
            const int kb = k8 * 8;
            unsigned a[2][4];
            #pragma unroll
            for (int mi = 0; mi < 2; mi++) {
                int m0 = warp * 32 + mi * 16;
                a[mi][0] = As[(m0 + g) * 68 + kb + tig];
                a[mi][1] = As[(m0 + g + 8) * 68 + kb + tig];
                a[mi][2] = As[(m0 + g) * 68 + kb + tig + 4];
                a[mi][3] = As[(m0 + g + 8) * 68 + kb + tig + 4];
            }
            #pragma unroll
            for (int nj = 0; nj < 8; nj++) {
                int n0 = nj * 8;
                unsigned bb[2];
                bb[0] = Vs[(kb + tig) * 72 + n0 + g];
                bb[1] = Vs[(kb + tig + 4) * 72 + n0 + g];
                #pragma unroll
                for (int mi = 0; mi < 2; mi++) mma8(acc[mi][nj], a[mi], bb);
            }
        }
        __syncthreads();
    }

    #pragma unroll
    for (int mi = 0; mi < 2; mi++) {
        #pragma unroll
        for (int nj = 0; nj < 8; nj++) {
            int m0 = t0 + warp * 32 + mi * 16;
            int n0 = nj * 8 + tig * 2;
            float* c = acc[mi][nj];
            size_t r0 = ((size_t)b * T_ + m0 + g) * H_ + n0;
            size_t r1 = ((size_t)b * T_ + m0 + g + 8) * H_ + n0;
            atomicAdd(&res[r0],     c[0]);
            atomicAdd(&res[r0 + 1], c[1]);
            atomicAdd(&res[r1],     c[2]);
            atomicAdd(&res[r1 + 1], c[3]);
        }
    }
}

// ---------------------------------------------------------------------------
extern "C" void kernel_launch(void* const* d_in, const int* in_sizes, int n_in,
                              void* d_out, int out_size) {
    (void)in_sizes; (void)n_in;
    const float* x  = (const float*)d_in[0];
    const float* Wq = (const float*)d_in[1];
    const float* Wk = (const float*)d_in[2];
    const float* Wv = (const float*)d_in[3];

    const size_t n_res  = (size_t)B_ * T_ * H_;
    const size_t n_attn = (size_t)B_ * T_ * T_;

    float* attn_scratch = nullptr;
    float* res_scratch = nullptr;
    float* rowsum = nullptr;
    cudaGetSymbolAddress((void**)&attn_scratch, g_attn_scratch);
    cudaGetSymbolAddress((void**)&res_scratch, g_res);
    cudaGetSymbolAddress((void**)&rowsum, g_rowsum);

    float* res;
    float* attn;
    if ((size_t)out_size == n_res + n_attn) {
        res  = (float*)d_out;
        attn = (float*)d_out + n_res;
    } else if ((size_t)out_size == n_attn) {
        attn = (float*)d_out;
        res  = res_scratch;
    } else {
        res  = (float*)d_out;
        attn = attn_scratch;
    }

    cudaFuncSetAttribute(proj_kernel,   cudaFuncAttributeMaxDynamicSharedMemorySize, PROJ_SMEM);
    cudaFuncSetAttribute(scores_kernel, cudaFuncAttributeMaxDynamicSharedMemorySize, SCORES_SMEM);
    cudaFuncSetAttribute(av_kernel,     cudaFuncAttributeMaxDynamicSharedMemorySize, AV_SMEM);

    cudaMemsetAsync(rowsum, 0, NROWS * sizeof(float));
    cudaMemsetAsync(res, 0, n_res * sizeof(float));
    proj_kernel<<<dim3(128, 3), 128, PROJ_SMEM>>>(x, Wq, Wk, Wv);
    scores_kernel<<<dim3(16, 32, 8), 128, SCORES_SMEM>>>(attn);
    av_kernel<<<dim3(4, 16, 8), 128, AV_SMEM>>>(attn, res);
}

// round 8
// speedup vs baseline: 1.2072x; 1.2072x over previous
#include <cuda_runtime.h>
#include <math.h>

#define B_ 8
#define T_ 2048
#define C_ 1024
#define H_ 64
#define NROWS (B_ * T_)   // 16384

__device__ float g_q[NROWS * H_];
__device__ float g_k[NROWS * H_];
__device__ float g_v[NROWS * H_];
__device__ float g_res[NROWS * H_];
__device__ float g_rowsum[NROWS];
__device__ float g_attn_scratch[(size_t)B_ * T_ * T_];

// ---- tf32 helpers -----------------------------------------------------------
__device__ __forceinline__ unsigned tf32(float f) {
    unsigned r;
    asm("cvt.rna.tf32.f32 %0, %1;" : "=r"(r) : "f"(f));
    return r;
}
__device__ __forceinline__ uint4 tf32x4(float4 f) {
    uint4 u;
    u.x = tf32(f.x); u.y = tf32(f.y); u.z = tf32(f.z); u.w = tf32(f.w);
    return u;
}
// D += A(16x8,row) * B(8x8,col); tf32 in, fp32 accum
__device__ __forceinline__ void mma8(float* c, const unsigned* a, const unsigned* b) {
    asm("mma.sync.aligned.m16n8k8.row.col.f32.tf32.tf32.f32 "
        "{%0,%1,%2,%3},{%4,%5,%6,%7},{%8,%9},{%0,%1,%2,%3};"
        : "+f"(c[0]), "+f"(c[1]), "+f"(c[2]), "+f"(c[3])
        : "r"(a[0]), "r"(a[1]), "r"(a[2]), "r"(a[3]), "r"(b[0]), "r"(b[1]));
}

// ---------------------------------------------------------------------------
// Kernel 1: QKV projection (round-7 version, 61us).
// grid=(128, 3), block=128 (4 warps: 2m x 2n). Block tile 128m x 64h.
// Warp tile 64m x 32h (mi=4, nj=4), LDS/MMA = 1.5.
// ---------------------------------------------------------------------------
#define PROJ_SMEM (128 * 68 * 4 + 64 * 72 * 4)   // 53248 B
__global__ __launch_bounds__(128) void proj_kernel(const float* __restrict__ x,
                                                   const float* __restrict__ Wq,
                                                   const float* __restrict__ Wk,
                                                   const float* __restrict__ Wv) {
    extern __shared__ unsigned smu[];
    unsigned* Xs = smu;             // [128][68]
    unsigned* Ws = smu + 128 * 68;  // [64][72]

    const float* W; float* out;
    if (blockIdx.y == 0)      { W = Wq; out = g_q; }
    else if (blockIdx.y == 1) { W = Wk; out = g_k; }
    else                      { W = Wv; out = g_v; }

    const int row0 = blockIdx.x * 128;
    const int tid  = threadIdx.x;
    const int warp = tid >> 5;
    const int lane = tid & 31;
    const int g    = lane >> 2;    // 0..7
    const int tig  = lane & 3;     // 0..3
    const int wm   = warp >> 1;    // 0..1 (m)
    const int wn   = warp & 1;     // 0..1 (n)

    float acc[4][4][4] = {};

    for (int k0 = 0; k0 < C_; k0 += 64) {
        #pragma unroll
        for (int it = 0; it < 16; it++) {
            int idx = tid + it * 128;         // 2048 float4 = 128 x 16
            int r = idx >> 4, c4 = idx & 15;
            *(uint4*)&Xs[r * 68 + c4 * 4] =
                tf32x4(*(const float4*)&x[(size_t)(row0 + r) * C_ + k0 + c4 * 4]);
        }
        #pragma unroll
        for (int it = 0; it < 8; it++) {
            int idx = tid + it * 128;         // 1024 float4 = 64 x 16
            int r = idx >> 4, c4 = idx & 15;
            *(uint4*)&Ws[r * 72 + c4 * 4] =
                tf32x4(*(const float4*)&W[(size_t)(k0 + r) * H_ + c4 * 4]);
        }
        __syncthreads();

        #pragma unroll
        for (int k8 = 0; k8 < 8; k8++) {
            const int kb = k8 * 8;
            unsigned a[4][4];
            #pragma unroll
            for (int mi = 0; mi < 4; mi++) {
                int m0 = wm * 64 + mi * 16;
                a[mi][0] = Xs[(m0 + g) * 68 + kb + tig];
                a[mi][1] = Xs[(m0 + g + 8) * 68 + kb + tig];
                a[mi][2] = Xs[(m0 + g) * 68 + kb + tig + 4];
                a[mi][3] = Xs[(m0 + g + 8) * 68 + kb + tig + 4];
            }
            #pragma unroll
            for (int nj = 0; nj < 4; nj++) {
                int n0 = wn * 32 + nj * 8;
                unsigned b[2];
                b[0] = Ws[(kb + tig) * 72 + n0 + g];
                b[1] = Ws[(kb + tig + 4) * 72 + n0 + g];
                #pragma unroll
                for (int mi = 0; mi < 4; mi++) mma8(acc[mi][nj], a[mi], b);
            }
        }
        __syncthreads();
    }

    #pragma unroll
    for (int mi = 0; mi < 4; mi++) {
        #pragma unroll
        for (int nj = 0; nj < 4; nj++) {
            int m0 = row0 + wm * 64 + mi * 16;
            int n0 = wn * 32 + nj * 8 + tig * 2;
            float* c = acc[mi][nj];
            *(float2*)&out[(size_t)(m0 + g) * H_ + n0]     = make_float2(c[0], c[1]);
            *(float2*)&out[(size_t)(m0 + g + 8) * H_ + n0] = make_float2(c[2], c[3]);
        }
    }
}

// ---------------------------------------------------------------------------
// Kernel 2: E = exp(Q@K^T / 32) lower tiles (zeros upper), rowsum atomics.
// grid=(16 s,32 t,8 b), block=128 (4 warps along s). Tile 64t x 128s.
// (round-6 version)
// ---------------------------------------------------------------------------
#define SCORES_SMEM (64 * 68 * 4 + 128 * 68 * 4)   // 52224 B
__global__ __launch_bounds__(128, 4) void scores_kernel(float* __restrict__ attn) {
    const int s_t = blockIdx.x, t_t = blockIdx.y;
    const int b = blockIdx.z;
    const int t0 = t_t * 64, s0 = s_t * 128;
    const int tid = threadIdx.x;

    if (s0 > t0 + 63) {  // strictly-upper tile: zero fill
        #pragma unroll
        for (int it = 0; it < 16; it++) {
            int idx = tid + it * 128;       // 2048 quads = 64 x 32
            int r = idx >> 5, c4 = idx & 31;
            *(float4*)&attn[((size_t)b * T_ + t0 + r) * T_ + s0 + c4 * 4] =
                make_float4(0.f, 0.f, 0.f, 0.f);
        }
        return;
    }

    extern __shared__ unsigned smu[];
    unsigned* Qs = smu;            // [64][68]
    unsigned* Ks = smu + 64 * 68;  // [128][68]

    const float* q = g_q + (size_t)b * T_ * H_;
    const float* k = g_k + (size_t)b * T_ * H_;

    #pragma unroll
    for (int it = 0; it < 8; it++) {
        int idx = tid + it * 128;          // 1024 float4 = 64 x 16
        int r = idx >> 4, c4 = idx & 15;
        *(uint4*)&Qs[r * 68 + c4 * 4] =
            tf32x4(*(const float4*)&q[(size_t)(t0 + r) * H_ + c4 * 4]);
    }
    #pragma unroll
    for (int it = 0; it < 16; it++) {
        int idx = tid + it * 128;          // 2048 float4 = 128 x 16
        int r = idx >> 4, c4 = idx & 15;
        *(uint4*)&Ks[r * 68 + c4 * 4] =
            tf32x4(*(const float4*)&k[(size_t)(s0 + r) * H_ + c4 * 4]);
    }
    __syncthreads();

    const int warp = tid >> 5;
    const int lane = tid & 31;
    const int g    = lane >> 2;
    const int tig  = lane & 3;

    float acc[4][4][4] = {};
    #pragma unroll
    for (int k8 = 0; k8 < 8; k8++) {
        const int kb = k8 * 8;
        unsigned a[4][4];
        #pragma unroll
        for (int mi = 0; mi < 4; mi++) {
            int m0 = mi * 16;
            a[mi][0] = Qs[(m0 + g) * 68 + kb + tig];
            a[mi][1] = Qs[(m0 + g + 8) * 68 + kb + tig];
            a[mi][2] = Qs[(m0 + g) * 68 + kb + tig + 4];
            a[mi][3] = Qs[(m0 + g + 8) * 68 + kb + tig + 4];
        }
        #pragma unroll
        for (int nj = 0; nj < 4; nj++) {
            int n0 = warp * 32 + nj * 8;
            unsigned bb[2];
            bb[0] = Ks[(n0 + g) * 68 + kb + tig];
            bb[1] = Ks[(n0 + g) * 68 + kb + tig + 4];
            #pragma unroll
            for (int mi = 0; mi < 4; mi++) mma8(acc[mi][nj], a[mi], bb);
        }
    }

    const float sc = 0.03125f;  // 1/sqrt(1024)
    const bool need_mask = (s0 + 127 > t0);
    #pragma unroll
    for (int mi = 0; mi < 4; mi++) {
        const int trow0 = t0 + mi * 16 + g;
        const int trow1 = trow0 + 8;
        float rs0 = 0.f, rs1 = 0.f;
        #pragma unroll
        for (int nj = 0; nj < 4; nj++) {
            int col = s0 + warp * 32 + nj * 8 + tig * 2;
            float* c = acc[mi][nj];
            float e0 = (!need_mask || col     <= trow0) ? __expf(c[0] * sc) : 0.f;
            float e1 = (!need_mask || col + 1 <= trow0) ? __expf(c[1] * sc) : 0.f;
            float e2 = (!need_mask || col     <= trow1) ? __expf(c[2] * sc) : 0.f;
            float e3 = (!need_mask || col + 1 <= trow1) ? __expf(c[3] * sc) : 0.f;
            rs0 += e0 + e1; rs1 += e2 + e3;
            *(float2*)&attn[((size_t)b * T_ + trow0) * T_ + col] = make_float2(e0, e1);
            *(float2*)&attn[((size_t)b * T_ + trow1) * T_ + col] = make_float2(e2, e3);
        }
        rs0 += __shfl_xor_sync(0xffffffffu, rs0, 1);
        rs0 += __shfl_xor_sync(0xffffffffu, rs0, 2);
        rs1 += __shfl_xor_sync(0xffffffffu, rs1, 1);
        rs1 += __shfl_xor_sync(0xffffffffu, rs1, 2);
        if (tig == 0) {
            atomicAdd(&g_rowsum[(size_t)b * T_ + trow0], rs0);
            atomicAdd(&g_rowsum[(size_t)b * T_ + trow1], rs1);
        }
    }
}

// ---------------------------------------------------------------------------
// Kernel 3: res += (attn/rowsum) @ V, split-K over 512-wide s-spans.
// Fused normalization. grid=(4 spans, 32 t desc, 8 b), block=128 (4 warps 2x2).
// Tile 64t x 64h. (round-6 version)
// ---------------------------------------------------------------------------
#define AV_SMEM (64 * 68 * 4 + 64 * 72 * 4 + 64 * 4)   // 35904 B
__global__ __launch_bounds__(128, 5) void av_kernel(float* __restrict__ attn,
                                                    float* __restrict__ res) {
    const int sc   = blockIdx.x;
    const int t_t  = 31 - blockIdx.y;   // big tiles first
    const int b    = blockIdx.z;
    const int t0   = t_t * 64;
    if (sc * 512 > t0 + 63) return;

    extern __shared__ unsigned smu[];
    unsigned* As = smu;            // [64 t][68 s] tf32
    unsigned* Vs = smu + 64 * 68;  // [64 s][72 h] tf32
    float* sinv  = (float*)(smu + 64 * 68 + 64 * 72);

    const int tid = threadIdx.x;
    if (tid < 64) sinv[tid] = 1.f / g_rowsum[(size_t)b * T_ + t0 + tid];
    __syncthreads();

    const float* v = g_v + (size_t)b * T_ * H_;
    const int warp = tid >> 5;
    const int lane = tid & 31;
    const int g    = lane >> 2;
    const int tig  = lane & 3;
    const int wm   = warp >> 1;   // 0..1
    const int wn   = warp & 1;    // 0..1

    float acc[2][4][4] = {};

    #pragma unroll
    for (int c2 = 0; c2 < 8; c2++) {
        const int s0 = sc * 512 + c2 * 64;
        if (s0 > t0 + 63) break;

        #pragma unroll
        for (int it = 0; it < 8; it++) {
            int idx = tid + it * 128;          // 1024 float4 = 64 x 16
            int r = idx >> 4, c4 = idx & 15;
            float* ap = &attn[((size_t)b * T_ + t0 + r) * T_ + s0 + c4 * 4];
            float4 f = *(const float4*)ap;
            float iv = sinv[r];
            f = make_float4(f.x * iv, f.y * iv, f.z * iv, f.w * iv);
            *(float4*)ap = f;                  // normalized fp32 back to gmem
            *(uint4*)&As[r * 68 + c4 * 4] = tf32x4(f);
        }
        #pragma unroll
        for (int it = 0; it < 8; it++) {
            int idx = tid + it * 128;
            int r = idx >> 4, c4 = idx & 15;
            *(uint4*)&Vs[r * 72 + c4 * 4] =
                tf32x4(*(const float4*)&v[(size_t)(s0 + r) * H_ + c4 * 4]);
        }
        __syncthreads();

        #pragma unroll
        for (int k8 = 0; k8 < 8; k8++) {
            const int kb = k8 * 8;
            unsigned a[2][4];
            #pragma unroll
            for (int mi = 0; mi < 2; mi++) {
                int m0 = wm * 32 + mi * 16;
                a[mi][0] = As[(m0 + g) * 68 + kb + tig];
                a[mi][1] = As[(m0 + g + 8) * 68 + kb + tig];
                a[mi][2] = As[(m0 + g) * 68 + kb + tig + 4];
                a[mi][3] = As[(m0 + g + 8) * 68 + kb + tig + 4];
            }
            #pragma unroll
            for (int nj = 0; nj < 4; nj++) {
                int n0 = wn * 32 + nj * 8;
                unsigned bb[2];
                bb[0] = Vs[(kb + tig) * 72 + n0 + g];
                bb[1] = Vs[(kb + tig + 4) * 72 + n0 + g];
                #pragma unroll
                for (int mi = 0; mi < 2; mi++) mma8(acc[mi][nj], a[mi], bb);
            }
        }
        __syncthreads();
    }

    #pragma unroll
    for (int mi = 0; mi < 2; mi++) {
        #pragma unroll
        for (int nj = 0; nj < 4; nj++) {
            int m0 = t0 + wm * 32 + mi * 16;
            int n0 = wn * 32 + nj * 8 + tig * 2;
            float* c = acc[mi][nj];
            size_t r0 = ((size_t)b * T_ + m0 + g) * H_ + n0;
            size_t r1 = ((size_t)b * T_ + m0 + g + 8) * H_ + n0;
            atomicAdd(&res[r0],     c[0]);
            atomicAdd(&res[r0 + 1], c[1]);
            atomicAdd(&res[r1],     c[2]);
            atomicAdd(&res[r1 + 1], c[3]);
        }
    }
}

// ---------------------------------------------------------------------------
extern "C" void kernel_launch(void* const* d_in, const int* in_sizes, int n_in,
                              void* d_out, int out_size) {
    (void)in_sizes; (void)n_in;
    const float* x  = (const float*)d_in[0];
    const float* Wq = (const float*)d_in[1];
    const float* Wk = (const float*)d_in[2];
    const float* Wv = (const float*)d_in[3];

    const size_t n_res  = (size_t)B_ * T_ * H_;
    const size_t n_attn = (size_t)B_ * T_ * T_;

    float* attn_scratch = nullptr;
    float* res_scratch = nullptr;
    float* rowsum = nullptr;
    cudaGetSymbolAddress((void**)&attn_scratch, g_attn_scratch);
    cudaGetSymbolAddress((void**)&res_scratch, g_res);
    cudaGetSymbolAddress((void**)&rowsum, g_rowsum);

    float* res;
    float* attn;
    if ((size_t)out_size == n_res + n_attn) {
        res  = (float*)d_out;
        attn = (float*)d_out + n_res;
    } else if ((size_t)out_size == n_attn) {
        attn = (float*)d_out;
        res  = res_scratch;
    } else {
        res  = (float*)d_out;
        attn = attn_scratch;
    }

    cudaFuncSetAttribute(proj_kernel,   cudaFuncAttributeMaxDynamicSharedMemorySize, PROJ_SMEM);
    cudaFuncSetAttribute(scores_kernel, cudaFuncAttributeMaxDynamicSharedMemorySize, SCORES_SMEM);
    cudaFuncSetAttribute(av_kernel,     cudaFuncAttributeMaxDynamicSharedMemorySize, AV_SMEM);

    cudaMemsetAsync(rowsum, 0, NROWS * sizeof(float));
    cudaMemsetAsync(res, 0, n_res * sizeof(float));
    proj_kernel<<<dim3(128, 3), 128, PROJ_SMEM>>>(x, Wq, Wk, Wv);
    scores_kernel<<<dim3(16, 32, 8), 128, SCORES_SMEM>>>(attn);
    av_kernel<<<dim3(4, 32, 8), 128, AV_SMEM>>>(attn, res);
}